// round 16
// baseline (speedup 1.0000x reference)
#include <cuda_runtime.h>

// Problem dims (fixed by the dataset)
#define T_STEPS 20
#define BATCH   512
#define DIN     4096
#define HDIM    1024
#define CDIM    100
#define MROWS   (T_STEPS * BATCH)   // 10240
#define KSPLIT  4
#define KCHUNK  (DIN / KSPLIT)      // 1024
#define HELEMS  ((size_t)MROWS * HDIM)   // 10,485,760

// -------- scratch (static __device__ globals; no runtime allocation) --------
__device__ float g_Hp[KSPLIT * HELEMS];          // split-K partials (160 MB)
__device__ float g_H[HELEMS];                    // merged fc1 outputs (40 MB)
__device__ float g_mean[T_STEPS * HDIM];
__device__ float g_istd[T_STEPS * HDIM];
__device__ float g_S[BATCH * HDIM];              // spike counts
__device__ float g_W2T[HDIM * 128];              // W2 transposed, padded to 128 cols

// ============================================================================
// Kernel 1: split-K partials of C[10240,1024] = A * W1^T   (fp32, FFMA2)
// R13 structure (tile 128x128, BK=16, 256 thr, 8x8/thread, split-K=4, XOR
// swizzle) with ONE change: A is stored DUPLICATED in smem
// (As[k][2m]=As[k][2m+1]=A[m][k], 16x256 floats) so the inner loop loads
// ready-made f32x2 A-pairs via ld.shared.v2.b64 and issues ZERO mov.b64
// duplications (was 16 ALU MOVs per thread per k). FFMA2 operand values and
// order are identical -> bit-identical results.
// Smem: As 2x16KB + Bs 2x8KB = 49152 B static (the 48KB limit, exactly).
// ============================================================================
__device__ __forceinline__ void sts_tile(
    float (*As)[16][256], float (*Bs)[16][128], int buf, int lk, int lmx,
    const float4& ar0, const float4& ar1, const float4& br0, const float4& br1)
{
    // A duplicated: column pair [2*lmx, 2*lmx+1]; second m-group at +64 cols
    // (bit 6 of lm untouched by the swizzle mask, so (lm+64)^msk = lmx+64).
    *(float2*)&As[buf][lk + 0][2 * lmx]       = make_float2(ar0.x, ar0.x);
    *(float2*)&As[buf][lk + 1][2 * lmx]       = make_float2(ar0.y, ar0.y);
    *(float2*)&As[buf][lk + 2][2 * lmx]       = make_float2(ar0.z, ar0.z);
    *(float2*)&As[buf][lk + 3][2 * lmx]       = make_float2(ar0.w, ar0.w);
    *(float2*)&As[buf][lk + 0][2 * lmx + 128] = make_float2(ar1.x, ar1.x);
    *(float2*)&As[buf][lk + 1][2 * lmx + 128] = make_float2(ar1.y, ar1.y);
    *(float2*)&As[buf][lk + 2][2 * lmx + 128] = make_float2(ar1.z, ar1.z);
    *(float2*)&As[buf][lk + 3][2 * lmx + 128] = make_float2(ar1.w, ar1.w);
    Bs[buf][lk + 0][lmx] = br0.x;  Bs[buf][lk + 1][lmx] = br0.y;
    Bs[buf][lk + 2][lmx] = br0.z;  Bs[buf][lk + 3][lmx] = br0.w;
    Bs[buf][lk + 0][lmx + 64] = br1.x;  Bs[buf][lk + 1][lmx + 64] = br1.y;
    Bs[buf][lk + 2][lmx + 64] = br1.z;  Bs[buf][lk + 3][lmx + 64] = br1.w;
}

__global__ __launch_bounds__(256, 2)
void gemm1_kernel(const float* __restrict__ A, const float* __restrict__ W1)
{
    __shared__ __align__(16) float As[2][16][256];   // duplicated A
    __shared__ __align__(16) float Bs[2][16][128];

    const int tid = threadIdx.x;
    const int bm  = blockIdx.y;   // 0..79
    const int bn  = blockIdx.x;   // 0..7
    const int kc  = blockIdx.z;   // 0..3  (K chunk)

    const int lm = tid >> 2;           // 0..63
    const int lk = (tid & 3) << 2;     // 0,4,8,12
    const int lmx = lm ^ (lk << 1);    // swizzled smem column (pair index)

    const float* Ap0 = A  + (size_t)(bm * 128 + lm) * DIN + kc * KCHUNK + lk;
    const float* Ap1 = Ap0 + (size_t)64 * DIN;
    const float* Bp0 = W1 + (size_t)(bn * 128 + lm) * DIN + kc * KCHUNK + lk;
    const float* Bp1 = Bp0 + (size_t)64 * DIN;

    const int warp = tid >> 5;
    const int lane = tid & 31;
    const int m0 = (warp >> 1) * 32 + (lane >> 3) * 8;   // mult of 8
    const int n0 = (warp & 1) * 64 + (lane & 7) * 4;     // mult of 4

    const unsigned as_base = (unsigned)__cvta_generic_to_shared(&As[0][0][0]);
    const unsigned bs_base = (unsigned)__cvta_generic_to_shared(&Bs[0][0][0]);

    unsigned long long acc[8][4];
#pragma unroll
    for (int i = 0; i < 8; i++)
#pragma unroll
        for (int j = 0; j < 4; j++) acc[i][j] = 0ull;

    float4 ar0 = *(const float4*)Ap0;
    float4 ar1 = *(const float4*)Ap1;
    float4 br0 = *(const float4*)Bp0;
    float4 br1 = *(const float4*)Bp1;
    sts_tile(As, Bs, 0, lk, lmx, ar0, ar1, br0, br1);
    __syncthreads();

    const int KT = KCHUNK / 16;   // 64
    int buf = 0;
    for (int kt = 0; kt < KT; kt++) {
        if (kt + 1 < KT) {
            Ap0 += 16; Ap1 += 16; Bp0 += 16; Bp1 += 16;
            ar0 = *(const float4*)Ap0;
            ar1 = *(const float4*)Ap1;
            br0 = *(const float4*)Bp0;
            br1 = *(const float4*)Bp1;
        }

        const unsigned abuf = as_base + (unsigned)(buf * 16 * 256 * 4);
        const unsigned bbuf = bs_base + (unsigned)(buf * 16 * 128 * 4);
#pragma unroll
        for (int k = 0; k < 16; k++) {
            const int sw = (k & 12) << 1;                 // compile-time per k
            // A pairs: 16 floats = 8 duplicated pairs for m0..m0+7
            const unsigned aaddr =
                abuf + (unsigned)((k * 256 + 2 * (m0 ^ sw)) * 4);
            unsigned long long ad0, ad1, ad2, ad3, ad4, ad5, ad6, ad7;
            asm("ld.shared.v2.b64 {%0, %1}, [%2];"
                : "=l"(ad0), "=l"(ad1) : "r"(aaddr));
            asm("ld.shared.v2.b64 {%0, %1}, [%2];"
                : "=l"(ad2), "=l"(ad3) : "r"(aaddr + 16));
            asm("ld.shared.v2.b64 {%0, %1}, [%2];"
                : "=l"(ad4), "=l"(ad5) : "r"(aaddr + 32));
            asm("ld.shared.v2.b64 {%0, %1}, [%2];"
                : "=l"(ad6), "=l"(ad7) : "r"(aaddr + 48));

            unsigned long long bp0, bp1, bp2, bp3;
            const unsigned baddr = bbuf + (unsigned)((k * 128 + (n0 ^ sw)) * 4);
            asm("ld.shared.v2.b64 {%0, %1}, [%2];"
                : "=l"(bp0), "=l"(bp1) : "r"(baddr));
            asm("ld.shared.v2.b64 {%0, %1}, [%2];"
                : "=l"(bp2), "=l"(bp3) : "r"(baddr + 128));

            const unsigned long long ad[8] =
                {ad0, ad1, ad2, ad3, ad4, ad5, ad6, ad7};
#pragma unroll
            for (int i = 0; i < 8; i++) {
                asm("fma.rn.f32x2 %0, %1, %2, %0;" : "+l"(acc[i][0]) : "l"(ad[i]), "l"(bp0));
                asm("fma.rn.f32x2 %0, %1, %2, %0;" : "+l"(acc[i][1]) : "l"(ad[i]), "l"(bp1));
                asm("fma.rn.f32x2 %0, %1, %2, %0;" : "+l"(acc[i][2]) : "l"(ad[i]), "l"(bp2));
                asm("fma.rn.f32x2 %0, %1, %2, %0;" : "+l"(acc[i][3]) : "l"(ad[i]), "l"(bp3));
            }
        }

        if (kt + 1 < KT) {
            sts_tile(As, Bs, buf ^ 1, lk, lmx, ar0, ar1, br0, br1);
        }
        __syncthreads();
        buf ^= 1;
    }

    float* Hp = g_Hp + (size_t)kc * HELEMS;
#pragma unroll
    for (int i = 0; i < 8; i++) {
        float* r = Hp + (size_t)(bm * 128 + m0 + i) * HDIM + bn * 128 + n0;
        *(unsigned long long*)(r)      = acc[i][0];
        *(unsigned long long*)(r + 2)  = acc[i][1];
        *(unsigned long long*)(r + 32) = acc[i][2];
        *(unsigned long long*)(r + 34) = acc[i][3];
    }
}

// ============================================================================
// Kernel 1b: deterministic split-K merge (R13 verbatim — wide parallelism:
// 10240 blocks; the R15 fusion starved this traffic of threads)
// ============================================================================
__global__ void merge_kernel()
{
    const size_t i = ((size_t)blockIdx.x * 256 + threadIdx.x) * 4;
    const float4 p0 = *(const float4*)(g_Hp + i);
    const float4 p1 = *(const float4*)(g_Hp + HELEMS + i);
    const float4 p2 = *(const float4*)(g_Hp + 2 * HELEMS + i);
    const float4 p3 = *(const float4*)(g_Hp + 3 * HELEMS + i);
    float4 s;
    s.x = ((p0.x + p1.x) + p2.x) + p3.x;
    s.y = ((p0.y + p1.y) + p2.y) + p3.y;
    s.z = ((p0.z + p1.z) + p2.z) + p3.z;
    s.w = ((p0.w + p1.w) + p2.w) + p3.w;
    *(float4*)(g_H + i) = s;
}

// ============================================================================
// Kernel 2: batch-norm stats per (t, j)   (R13 verbatim)
// ============================================================================
__global__ void bn_stats_kernel()
{
    const int t  = blockIdx.y;
    const int j2 = blockIdx.x * 128 + threadIdx.x;   // 0..511 (column pair)
    const float2* col = (const float2*)(g_H + (size_t)t * BATCH * HDIM) + j2;

    float s0 = 0.f, s1 = 0.f, q0 = 0.f, q1 = 0.f;
#pragma unroll 8
    for (int b = 0; b < BATCH; b++) {
        const float2 v = col[b * (HDIM / 2)];
        s0 += v.x;  q0 += v.x * v.x;
        s1 += v.y;  q1 += v.y * v.y;
    }
    const float inv = 1.0f / (float)BATCH;
    const float m0 = s0 * inv, m1 = s1 * inv;
    const int j = j2 * 2;
    g_mean[t * HDIM + j]     = m0;
    g_mean[t * HDIM + j + 1] = m1;
    g_istd[t * HDIM + j]     = rsqrtf(q0 * inv - m0 * m0 + 1e-4f);
    g_istd[t * HDIM + j + 1] = rsqrtf(q1 * inv - m1 * m1 + 1e-4f);
}

// ============================================================================
// Kernel 3: LIF recurrence -> spike counts S[b,j]   (unchanged)
// ============================================================================
__global__ void recurrence_kernel(const float* __restrict__ gamma)
{
    const int idx = blockIdx.x * 256 + threadIdx.x;   // b*1024 + j
    const int j = idx & (HDIM - 1);

    float mem = 0.f;
    float cnt = 0.f;
#pragma unroll
    for (int t = 0; t < T_STEPS; t++) {
        const float h  = g_H[(size_t)t * (BATCH * HDIM) + idx];
        const float hn = gamma[t * HDIM + j] * (h - g_mean[t * HDIM + j]) *
                         g_istd[t * HDIM + j];
        mem = 0.95f * mem + hn;
        if (mem > 1.0f) { cnt += 1.0f; mem -= 1.0f; }
    }
    g_S[idx] = cnt;
}

// ============================================================================
// Kernel 4a: transpose W2 [100,1024] -> W2T [1024,128]   (unchanged)
// ============================================================================
__global__ void transposeW2_kernel(const float* __restrict__ W2)
{
    const int idx = blockIdx.x * 256 + threadIdx.x;   // 0..131071
    const int k = idx >> 7;
    const int c = idx & 127;
    g_W2T[idx] = (c < CDIM) ? W2[c * HDIM + k] : 0.0f;
}

// ============================================================================
// Kernel 4b: out[b,c] = (1/T) * sum_k S[b,k] * W2T[k,c]   (unchanged)
// ============================================================================
__global__ void out_gemm_kernel(float* __restrict__ out)
{
    __shared__ float sS[8][HDIM];
    const int bb  = blockIdx.x;       // 0..63
    const int tid = threadIdx.x;

    for (int i = tid; i < 8 * HDIM; i += 256) {
        const int r = i >> 10, c = i & (HDIM - 1);
        sS[r][c] = g_S[(bb * 8 + r) * HDIM + c];
    }
    __syncthreads();

    const int br = tid >> 5;   // 0..7
    const int cq = tid & 31;   // 0..31 (25 active -> 100 cols)

    float4 acc = make_float4(0.f, 0.f, 0.f, 0.f);
#pragma unroll 8
    for (int k = 0; k < HDIM; k++) {
        const float  s = sS[br][k];                                 // broadcast
        const float4 w = *(const float4*)&g_W2T[k * 128 + cq * 4];  // coalesced
        acc.x += s * w.x;  acc.y += s * w.y;
        acc.z += s * w.z;  acc.w += s * w.w;
    }
    if (cq < 25) {
        const float sc = 1.0f / (float)T_STEPS;
        float4 o = make_float4(acc.x * sc, acc.y * sc, acc.z * sc, acc.w * sc);
        *(float4*)&out[(bb * 8 + br) * CDIM + cq * 4] = o;
    }
}

// ============================================================================
// launch
// ============================================================================
extern "C" void kernel_launch(void* const* d_in, const int* in_sizes, int n_in,
                              void* d_out, int out_size)
{
    const float* z     = (const float*)d_in[0];   // [20,512,4096]
    const float* W1    = (const float*)d_in[1];   // [1024,4096]
    const float* gamma = (const float*)d_in[2];   // [20,1024]
    const float* W2    = (const float*)d_in[3];   // [100,1024]
    float* out = (float*)d_out;                   // [512,100]

    gemm1_kernel<<<dim3(8, 80, KSPLIT), 256>>>(z, W1);
    merge_kernel<<<(unsigned)(HELEMS / 4 / 256), 256>>>();
    bn_stats_kernel<<<dim3(4, 20), 128>>>();
    recurrence_kernel<<<(BATCH * HDIM) / 256, 256>>>(gamma);
    transposeW2_kernel<<<(HDIM * 128) / 256, 256>>>(W2);
    out_gemm_kernel<<<BATCH / 8, 256>>>(out);
}

// round 17
// speedup vs baseline: 1.0645x; 1.0645x over previous
#include <cuda_runtime.h>

// Problem dims (fixed by the dataset)
#define T_STEPS 20
#define BATCH   512
#define DIN     4096
#define HDIM    1024
#define CDIM    100
#define MROWS   (T_STEPS * BATCH)   // 10240
#define KSPLIT  4
#define KCHUNK  (DIN / KSPLIT)      // 1024
#define HELEMS  ((size_t)MROWS * HDIM)   // 10,485,760

// -------- scratch (static __device__ globals; no runtime allocation) --------
__device__ float g_Hp[KSPLIT * HELEMS];          // split-K partials (160 MB)
__device__ float g_H[HELEMS];                    // merged fc1 outputs (40 MB)
__device__ float g_mean[T_STEPS * HDIM];
__device__ float g_istd[T_STEPS * HDIM];
__device__ float g_S[BATCH * HDIM];              // spike counts
__device__ float g_W2T[HDIM * 128];              // W2 transposed, padded to 128 cols

// ============================================================================
// Kernel 1: split-K partials of C[10240,1024] = A * W1^T   (fp32, FFMA2)
// R13 GEMM VERBATIM — measured best (~1520us). FMA-pipe-bound at rt=2 with
// issue slack; 3 attempted inner-loop variants all regressed (DRAM / regs /
// crossbar respectively). FROZEN.
// ============================================================================
__device__ __forceinline__ void sts_tile(
    float (*As)[16][128], float (*Bs)[16][128], int buf, int lk, int lmx,
    const float4& ar0, const float4& ar1, const float4& br0, const float4& br1)
{
    As[buf][lk + 0][lmx] = ar0.x;  As[buf][lk + 1][lmx] = ar0.y;
    As[buf][lk + 2][lmx] = ar0.z;  As[buf][lk + 3][lmx] = ar0.w;
    As[buf][lk + 0][lmx + 64] = ar1.x;  As[buf][lk + 1][lmx + 64] = ar1.y;
    As[buf][lk + 2][lmx + 64] = ar1.z;  As[buf][lk + 3][lmx + 64] = ar1.w;
    Bs[buf][lk + 0][lmx] = br0.x;  Bs[buf][lk + 1][lmx] = br0.y;
    Bs[buf][lk + 2][lmx] = br0.z;  Bs[buf][lk + 3][lmx] = br0.w;
    Bs[buf][lk + 0][lmx + 64] = br1.x;  Bs[buf][lk + 1][lmx + 64] = br1.y;
    Bs[buf][lk + 2][lmx + 64] = br1.z;  Bs[buf][lk + 3][lmx + 64] = br1.w;
}

__global__ __launch_bounds__(256, 2)
void gemm1_kernel(const float* __restrict__ A, const float* __restrict__ W1)
{
    __shared__ __align__(16) float As[2][16][128];
    __shared__ __align__(16) float Bs[2][16][128];

    const int tid = threadIdx.x;
    const int bm  = blockIdx.y;   // 0..79
    const int bn  = blockIdx.x;   // 0..7
    const int kc  = blockIdx.z;   // 0..3  (K chunk)

    const int lm = tid >> 2;           // 0..63
    const int lk = (tid & 3) << 2;     // 0,4,8,12
    const int lmx = lm ^ (lk << 1);    // swizzled smem column

    const float* Ap0 = A  + (size_t)(bm * 128 + lm) * DIN + kc * KCHUNK + lk;
    const float* Ap1 = Ap0 + (size_t)64 * DIN;
    const float* Bp0 = W1 + (size_t)(bn * 128 + lm) * DIN + kc * KCHUNK + lk;
    const float* Bp1 = Bp0 + (size_t)64 * DIN;

    const int warp = tid >> 5;
    const int lane = tid & 31;
    const int m0 = (warp >> 1) * 32 + (lane >> 3) * 8;   // mult of 8
    const int n0 = (warp & 1) * 64 + (lane & 7) * 4;     // mult of 4

    const unsigned bs_base =
        (unsigned)__cvta_generic_to_shared(&Bs[0][0][0]);

    unsigned long long acc[8][4];
#pragma unroll
    for (int i = 0; i < 8; i++)
#pragma unroll
        for (int j = 0; j < 4; j++) acc[i][j] = 0ull;

    float4 ar0 = *(const float4*)Ap0;
    float4 ar1 = *(const float4*)Ap1;
    float4 br0 = *(const float4*)Bp0;
    float4 br1 = *(const float4*)Bp1;
    sts_tile(As, Bs, 0, lk, lmx, ar0, ar1, br0, br1);
    __syncthreads();

    const int KT = KCHUNK / 16;   // 64
    int buf = 0;
    for (int kt = 0; kt < KT; kt++) {
        if (kt + 1 < KT) {
            Ap0 += 16; Ap1 += 16; Bp0 += 16; Bp1 += 16;
            ar0 = *(const float4*)Ap0;
            ar1 = *(const float4*)Ap1;
            br0 = *(const float4*)Bp0;
            br1 = *(const float4*)Bp1;
        }

        const float* Asb = &As[buf][0][0];
        const unsigned bbuf = bs_base + (unsigned)(buf * 16 * 128 * 4);
#pragma unroll
        for (int k = 0; k < 16; k++) {
            const int sw = (k & 12) << 1;                 // compile-time per k
            const float4 a0 = *(const float4*)(Asb + k * 128 + (m0 ^ sw));
            const float4 a1 = *(const float4*)(Asb + k * 128 + (m0 ^ sw) + 4);
            unsigned long long bp0, bp1, bp2, bp3;
            const unsigned addr = bbuf + (unsigned)((k * 128 + (n0 ^ sw)) * 4);
            asm("ld.shared.v2.b64 {%0, %1}, [%2];"
                : "=l"(bp0), "=l"(bp1) : "r"(addr));
            asm("ld.shared.v2.b64 {%0, %1}, [%2];"
                : "=l"(bp2), "=l"(bp3) : "r"(addr + 128));

            const float av[8] = {a0.x, a0.y, a0.z, a0.w, a1.x, a1.y, a1.z, a1.w};
#pragma unroll
            for (int i = 0; i < 8; i++) {
                unsigned long long ad;
                asm("mov.b64 %0, {%1, %1};"
                    : "=l"(ad) : "r"(__float_as_uint(av[i])));
                asm("fma.rn.f32x2 %0, %1, %2, %0;" : "+l"(acc[i][0]) : "l"(ad), "l"(bp0));
                asm("fma.rn.f32x2 %0, %1, %2, %0;" : "+l"(acc[i][1]) : "l"(ad), "l"(bp1));
                asm("fma.rn.f32x2 %0, %1, %2, %0;" : "+l"(acc[i][2]) : "l"(ad), "l"(bp2));
                asm("fma.rn.f32x2 %0, %1, %2, %0;" : "+l"(acc[i][3]) : "l"(ad), "l"(bp3));
            }
        }

        if (kt + 1 < KT) {
            sts_tile(As, Bs, buf ^ 1, lk, lmx, ar0, ar1, br0, br1);
        }
        __syncthreads();
        buf ^= 1;
    }

    float* Hp = g_Hp + (size_t)kc * HELEMS;
#pragma unroll
    for (int i = 0; i < 8; i++) {
        float* r = Hp + (size_t)(bm * 128 + m0 + i) * HDIM + bn * 128 + n0;
        *(unsigned long long*)(r)      = acc[i][0];
        *(unsigned long long*)(r + 2)  = acc[i][1];
        *(unsigned long long*)(r + 32) = acc[i][2];
        *(unsigned long long*)(r + 34) = acc[i][3];
    }
}

// ============================================================================
// Kernel 2: fused split-K merge + batch-norm stats, EXACT-ORDER.
// grid (4, 20) x 256 threads: thread owns one (t, j) column. For b=0..511 in
// order: merge ((p0+p1)+p2)+p3 (identical to old merge_kernel element math),
// write g_H, accumulate s/q in the same b-order as the old bn_stats_kernel.
// -> mean/istd and g_H are BIT-IDENTICAL to the R13 pipeline, while the
// separate 40MB bn read pass disappears. 256-thr blocks + unroll-8 batched
// loads give ~2x the in-flight bytes of the failed R15 fusion (which used
// 128-thr blocks and starved DRAM at ~1.1 TB/s).
// ============================================================================
__global__ void merge_bn_kernel()
{
    const int t = blockIdx.y;                       // 0..19
    const int j = blockIdx.x * 256 + threadIdx.x;   // 0..1023
    const size_t plane = (size_t)t * BATCH * HDIM;
    const float* c0 = g_Hp + plane + j;
    const float* c1 = g_Hp + HELEMS + plane + j;
    const float* c2 = g_Hp + 2 * HELEMS + plane + j;
    const float* c3 = g_Hp + 3 * HELEMS + plane + j;
    float* ch = g_H + plane + j;

    float s = 0.f, q = 0.f;
#pragma unroll 8
    for (int b = 0; b < BATCH; b++) {
        const int off = b * HDIM;
        const float p0 = c0[off];
        const float p1 = c1[off];
        const float p2 = c2[off];
        const float p3 = c3[off];
        const float v = ((p0 + p1) + p2) + p3;   // identical merge order
        ch[off] = v;
        s += v;                                   // identical b-order
        q += v * v;
    }
    const float inv = 1.0f / (float)BATCH;
    const float m = s * inv;
    g_mean[t * HDIM + j] = m;
    g_istd[t * HDIM + j] = rsqrtf(q * inv - m * m + 1e-4f);
}

// ============================================================================
// Kernel 3: LIF recurrence -> spike counts, float2 (thread = j-pair).
// Per-(b,j) math is element-independent and untouched -> bit-identical S.
// Half the threads, 2x ILP per thread; g_H loads stay fully coalesced.
// ============================================================================
__global__ void recurrence_kernel(const float* __restrict__ gamma)
{
    const int idx2 = blockIdx.x * 256 + threadIdx.x;   // 0..(512*512-1)
    const int b  = idx2 >> 9;          // 0..511
    const int j2 = idx2 & 511;         // column pair index

    const float2* H2 = (const float2*)g_H;
    const float2* G2 = (const float2*)gamma;
    const float2* M2 = (const float2*)g_mean;
    const float2* I2 = (const float2*)g_istd;

    float2 mem = make_float2(0.f, 0.f);
    float2 cnt = make_float2(0.f, 0.f);
#pragma unroll
    for (int t = 0; t < T_STEPS; t++) {
        const float2 h = H2[(size_t)t * (BATCH * HDIM / 2) + b * (HDIM / 2) + j2];
        const float2 g = G2[t * (HDIM / 2) + j2];
        const float2 m = M2[t * (HDIM / 2) + j2];
        const float2 is = I2[t * (HDIM / 2) + j2];
        const float hn0 = g.x * (h.x - m.x) * is.x;
        const float hn1 = g.y * (h.y - m.y) * is.y;
        mem.x = 0.95f * mem.x + hn0;
        mem.y = 0.95f * mem.y + hn1;
        if (mem.x > 1.0f) { cnt.x += 1.0f; mem.x -= 1.0f; }
        if (mem.y > 1.0f) { cnt.y += 1.0f; mem.y -= 1.0f; }
    }
    ((float2*)g_S)[b * (HDIM / 2) + j2] = cnt;
}

// ============================================================================
// Kernel 4a: transpose W2 [100,1024] -> W2T [1024,128]   (unchanged)
// ============================================================================
__global__ void transposeW2_kernel(const float* __restrict__ W2)
{
    const int idx = blockIdx.x * 256 + threadIdx.x;   // 0..131071
    const int k = idx >> 7;
    const int c = idx & 127;
    g_W2T[idx] = (c < CDIM) ? W2[c * HDIM + k] : 0.0f;
}

// ============================================================================
// Kernel 4b: out[b,c] = (1/T) * sum_k S[b,k] * W2T[k,c]   (unchanged)
// ============================================================================
__global__ void out_gemm_kernel(float* __restrict__ out)
{
    __shared__ float sS[8][HDIM];
    const int bb  = blockIdx.x;       // 0..63
    const int tid = threadIdx.x;

    for (int i = tid; i < 8 * HDIM; i += 256) {
        const int r = i >> 10, c = i & (HDIM - 1);
        sS[r][c] = g_S[(bb * 8 + r) * HDIM + c];
    }
    __syncthreads();

    const int br = tid >> 5;   // 0..7
    const int cq = tid & 31;   // 0..31 (25 active -> 100 cols)

    float4 acc = make_float4(0.f, 0.f, 0.f, 0.f);
#pragma unroll 8
    for (int k = 0; k < HDIM; k++) {
        const float  s = sS[br][k];                                 // broadcast
        const float4 w = *(const float4*)&g_W2T[k * 128 + cq * 4];  // coalesced
        acc.x += s * w.x;  acc.y += s * w.y;
        acc.z += s * w.z;  acc.w += s * w.w;
    }
    if (cq < 25) {
        const float sc = 1.0f / (float)T_STEPS;
        float4 o = make_float4(acc.x * sc, acc.y * sc, acc.z * sc, acc.w * sc);
        *(float4*)&out[(bb * 8 + br) * CDIM + cq * 4] = o;
    }
}

// ============================================================================
// launch
// ============================================================================
extern "C" void kernel_launch(void* const* d_in, const int* in_sizes, int n_in,
                              void* d_out, int out_size)
{
    const float* z     = (const float*)d_in[0];   // [20,512,4096]
    const float* W1    = (const float*)d_in[1];   // [1024,4096]
    const float* gamma = (const float*)d_in[2];   // [20,1024]
    const float* W2    = (const float*)d_in[3];   // [100,1024]
    float* out = (float*)d_out;                   // [512,100]

    gemm1_kernel<<<dim3(8, 80, KSPLIT), 256>>>(z, W1);
    merge_bn_kernel<<<dim3(4, 20), 256>>>();
    recurrence_kernel<<<(BATCH * HDIM / 2) / 256, 256>>>(gamma);
    transposeW2_kernel<<<(HDIM * 128) / 256, 256>>>(W2);
    out_gemm_kernel<<<BATCH / 8, 256>>>(out);
}